// round 2
// baseline (speedup 1.0000x reference)
#include <cuda_runtime.h>
#include <cuda_bf16.h>

#define N_NODES 50000
#define N_EDGES 800000
#define D 128
#define N_LAYERS 3
#define N_GRAPHS 512
#define ND (N_NODES * D)

// ---------------- scratch (device globals; no allocation allowed) ----------------
__device__ float g_h[ND];         // post-GEMM features
__device__ float g_agg[ND];       // edge aggregation buffer
__device__ float g_x[ND];         // layer output ping buffer
__device__ float g_wt[N_LAYERS * D * D];  // W transposed: wt[l][k][o] = W[l][o][k]
__device__ float g_dis[N_NODES];  // deg^{-1/2}
__device__ int   g_deg[N_NODES];
__device__ int   g_rows[N_EDGES];
__device__ int   g_cols[N_EDGES];
__device__ float g_norm[N_EDGES];
__device__ float g_gsum[N_GRAPHS];
__device__ int   g_gcnt[N_GRAPHS];

// ---------------- zero kernels ----------------
__global__ void zero_agg_k() {
    int i = blockIdx.x * blockDim.x + threadIdx.x;
    if (i < ND / 4) ((float4*)g_agg)[i] = make_float4(0.f, 0.f, 0.f, 0.f);
}
__global__ void zero_misc_k() {
    int i = blockIdx.x * blockDim.x + threadIdx.x;
    if (i < N_NODES) g_deg[i] = 0;
    if (i < N_GRAPHS) { g_gsum[i] = 0.f; g_gcnt[i] = 0; }
}

// ---------------- W transpose: Wt[l][k][o] = Ws[l][o][k] ----------------
__global__ void wt_k(const float* __restrict__ Ws) {
    int i = blockIdx.x * blockDim.x + threadIdx.x;
    if (i >= N_LAYERS * D * D) return;
    int l = i / (D * D);
    int rem = i - l * (D * D);
    int o = rem / D;
    int k = rem - o * D;
    g_wt[l * D * D + k * D + o] = Ws[i];
}

// ---------------- edge prep: int32 indices + in-degree ----------------
__global__ void edge_prep_k(const int* __restrict__ ei) {
    int e = blockIdx.x * blockDim.x + threadIdx.x;
    if (e >= N_EDGES) return;
    int r = ei[e];
    int c = ei[N_EDGES + e];
    g_rows[e] = r;
    g_cols[e] = c;
    atomicAdd(&g_deg[c], 1);
}

__global__ void dis_k() {
    int i = blockIdx.x * blockDim.x + threadIdx.x;
    if (i >= N_NODES) return;
    // +1 self loop; deg >= 1 always
    g_dis[i] = rsqrtf((float)(g_deg[i] + 1));
}

__global__ void edge_norm_k() {
    int e = blockIdx.x * blockDim.x + threadIdx.x;
    if (e >= N_EDGES) return;
    g_norm[e] = g_dis[g_rows[e]] * g_dis[g_cols[e]];
}

// ---------------- SGEMM: H[n,128] = X[n,128] @ Wt (Wt is [k][o]) ----------------
// block = 256 threads, tile 128 rows x 128 cols, whole K=128 in one shot.
// dyn smem: xs[128][128] + ws[128][128] = 128 KB
__global__ void gemm_k(const float* __restrict__ X, const float* __restrict__ Wt,
                       float* __restrict__ H, int n) {
    extern __shared__ float sm[];
    float* xs = sm;             // [r][k] row-major, 128*128
    float* ws = sm + D * D;     // [k][o] row-major, 128*128

    int tid = threadIdx.x;
    int row0 = blockIdx.x * 128;

    // load X tile (coalesced float4, identical layout)
    #pragma unroll
    for (int it = 0; it < 16; it++) {
        int i = tid + it * 256;                 // float4 index in tile
        int r = i >> 5;                         // 32 float4 per row
        int koff = (i & 31) << 2;
        int rg = row0 + r;
        float4 v = make_float4(0.f, 0.f, 0.f, 0.f);
        if (rg < n) v = *(const float4*)(X + rg * D + koff);
        ((float4*)xs)[i] = v;
    }
    // load Wt tile
    #pragma unroll
    for (int it = 0; it < 16; it++) {
        int i = tid + it * 256;
        ((float4*)ws)[i] = ((const float4*)Wt)[i];
    }
    __syncthreads();

    int tx = tid & 15;        // output-col group (8 cols)
    int ty = tid >> 4;        // row group (8 rows)
    float acc[8][8];
    #pragma unroll
    for (int i = 0; i < 8; i++)
        #pragma unroll
        for (int j = 0; j < 8; j++) acc[i][j] = 0.f;

    const float* wsrow = ws + tx * 8;
    #pragma unroll 4
    for (int k = 0; k < D; k++) {
        float4 w0 = *(const float4*)(wsrow + k * D);
        float4 w1 = *(const float4*)(wsrow + k * D + 4);
        #pragma unroll
        for (int i = 0; i < 8; i++) {
            float xv = xs[(ty * 8 + i) * D + k];
            acc[i][0] += xv * w0.x; acc[i][1] += xv * w0.y;
            acc[i][2] += xv * w0.z; acc[i][3] += xv * w0.w;
            acc[i][4] += xv * w1.x; acc[i][5] += xv * w1.y;
            acc[i][6] += xv * w1.z; acc[i][7] += xv * w1.w;
        }
    }

    #pragma unroll
    for (int i = 0; i < 8; i++) {
        int r = row0 + ty * 8 + i;
        if (r < n) {
            float4 a = make_float4(acc[i][0], acc[i][1], acc[i][2], acc[i][3]);
            float4 b = make_float4(acc[i][4], acc[i][5], acc[i][6], acc[i][7]);
            *(float4*)(H + r * D + tx * 8)     = a;
            *(float4*)(H + r * D + tx * 8 + 4) = b;
        }
    }
}

// ---------------- edge scatter: warp per edge, v4 reduction ----------------
__global__ void scatter_k() {
    int gt = blockIdx.x * blockDim.x + threadIdx.x;
    int e = gt >> 5;
    int lane = gt & 31;
    if (e >= N_EDGES) return;
    int r = g_rows[e];
    int c = g_cols[e];
    float nm = g_norm[e];
    float4 v = *(const float4*)(g_h + r * D + lane * 4);
    v.x *= nm; v.y *= nm; v.z *= nm; v.w *= nm;
    float* dst = g_agg + c * D + lane * 4;
    asm volatile("red.global.add.v4.f32 [%0], {%1,%2,%3,%4};"
                 :: "l"(dst), "f"(v.x), "f"(v.y), "f"(v.z), "f"(v.w)
                 : "memory");
}

// ---------------- finalize: x = relu(agg + dis^2*h + b); agg = 0 ----------------
__global__ void finalize_k(const float* __restrict__ bias) {
    int id = blockIdx.x * blockDim.x + threadIdx.x;   // float4 index
    if (id >= ND / 4) return;
    int node = id >> 5;                               // 32 float4 per node
    int col4 = id & 31;
    float d = g_dis[node];
    float d2 = d * d;
    float4 a = ((float4*)g_agg)[id];
    float4 h = ((const float4*)g_h)[id];
    float4 b = ((const float4*)bias)[col4];
    float4 o;
    o.x = fmaxf(a.x + d2 * h.x + b.x, 0.f);
    o.y = fmaxf(a.y + d2 * h.y + b.y, 0.f);
    o.z = fmaxf(a.z + d2 * h.z + b.z, 0.f);
    o.w = fmaxf(a.w + d2 * h.w + b.w, 0.f);
    ((float4*)g_x)[id] = o;
    ((float4*)g_agg)[id] = make_float4(0.f, 0.f, 0.f, 0.f);  // ready for next layer
}

// ---------------- pooling: per-node dot with lin_w, atomic into graph slot ----------------
__global__ void pool_k(const int* __restrict__ batch, const float* __restrict__ lw) {
    int gt = blockIdx.x * blockDim.x + threadIdx.x;
    int node = gt >> 5;
    int lane = gt & 31;
    if (node >= N_NODES) return;
    float4 xv = ((const float4*)g_x)[node * 32 + lane];
    float4 wv = ((const float4*)lw)[lane];
    float s = xv.x * wv.x + xv.y * wv.y + xv.z * wv.z + xv.w * wv.w;
    #pragma unroll
    for (int o = 16; o > 0; o >>= 1) s += __shfl_xor_sync(0xFFFFFFFFu, s, o);
    if (lane == 0) {
        int g = batch[node];
        atomicAdd(&g_gsum[g], s);
        atomicAdd(&g_gcnt[g], 1);
    }
}

__global__ void final_k(const float* __restrict__ lb, float* __restrict__ out) {
    int g = blockIdx.x * blockDim.x + threadIdx.x;
    if (g >= N_GRAPHS) return;
    float c = fmaxf((float)g_gcnt[g], 1.0f);
    out[g] = g_gsum[g] / c + lb[0];
}

// ---------------- launcher ----------------
extern "C" void kernel_launch(void* const* d_in, const int* in_sizes, int n_in,
                              void* d_out, int out_size) {
    const float* x    = (const float*)d_in[0];
    const int*   ei   = (const int*)d_in[1];    // int32! (JAX x64 disabled)
    const int*   bat  = (const int*)d_in[2];    // int32!
    const float* Ws   = (const float*)d_in[3];
    const float* bs   = (const float*)d_in[4];
    const float* lw   = (const float*)d_in[5];
    const float* lb   = (const float*)d_in[6];
    float*       out  = (float*)d_out;

    static bool attr_set = false;
    if (!attr_set) {
        cudaFuncSetAttribute(gemm_k, cudaFuncAttributeMaxDynamicSharedMemorySize,
                             2 * D * D * (int)sizeof(float));
        attr_set = true;
    }

    // resolve device-global addresses (host side)
    float *h_p, *x_p, *wt_p;
    cudaGetSymbolAddress((void**)&h_p,  g_h);
    cudaGetSymbolAddress((void**)&x_p,  g_x);
    cudaGetSymbolAddress((void**)&wt_p, g_wt);

    // 1) zero scratch
    zero_agg_k<<<(ND / 4 + 255) / 256, 256>>>();
    zero_misc_k<<<(N_NODES + 255) / 256, 256>>>();

    // 2) transpose weights
    wt_k<<<(N_LAYERS * D * D + 255) / 256, 256>>>(Ws);

    // 3) edge preprocessing
    edge_prep_k<<<(N_EDGES + 255) / 256, 256>>>(ei);
    dis_k<<<(N_NODES + 255) / 256, 256>>>();
    edge_norm_k<<<(N_EDGES + 255) / 256, 256>>>();

    // 4) layers
    const int gemm_blocks = (N_NODES + 127) / 128;
    const int smem = 2 * D * D * (int)sizeof(float);
    const long long scatter_threads = (long long)N_EDGES * 32;
    const int scatter_blocks = (int)((scatter_threads + 255) / 256);

    for (int l = 0; l < N_LAYERS; l++) {
        const float* xin = (l == 0) ? x : x_p;
        gemm_k<<<gemm_blocks, 256, smem>>>(xin, wt_p + l * D * D, h_p, N_NODES);
        scatter_k<<<scatter_blocks, 256>>>();
        finalize_k<<<(ND / 4 + 255) / 256, 256>>>(bs + l * D);
    }

    // 5) pooling + output
    pool_k<<<(N_NODES * 32 + 255) / 256, 256>>>(bat, lw);
    final_k<<<(N_GRAPHS + 255) / 256, 256>>>(lb, out);
}

// round 4
// speedup vs baseline: 1.7104x; 1.7104x over previous
#include <cuda_runtime.h>
#include <cuda_bf16.h>

#define N_NODES 50000
#define N_EDGES 800000
#define D 128
#define N_LAYERS 3
#define N_GRAPHS 512
#define ND (N_NODES * D)

#define SCAN_BLK 512
#define SCAN_NBLK ((N_NODES + SCAN_BLK - 1) / SCAN_BLK)   // 98

// ---------------- scratch (device globals; no allocation allowed) ----------------
__device__ float  g_h[ND];                  // post-GEMM features
__device__ float  g_x[ND];                  // layer output buffer
__device__ float  g_wt[N_LAYERS * D * D];   // W transposed: wt[l][k][o] = W[l][o][k]
__device__ float  g_dis[N_NODES];           // deg^{-1/2} (incl. self-loop)
__device__ int    g_deg[N_NODES];           // in-degree (edges only)
__device__ int    g_cur[N_NODES];           // placement cursor
__device__ int    g_off[N_NODES + 1];       // CSR offsets (by dst)
__device__ int    g_bsum[SCAN_NBLK];        // scan block sums
__device__ float2 g_em[N_EDGES];            // per-slot: (src as int bits, norm)
__device__ float  g_gsum[N_GRAPHS];
__device__ int    g_gcnt[N_GRAPHS];

// ---------------- zero ----------------
__global__ void zero_misc_k() {
    int i = blockIdx.x * blockDim.x + threadIdx.x;
    if (i < N_NODES) { g_deg[i] = 0; g_cur[i] = 0; }
    if (i < N_GRAPHS) { g_gsum[i] = 0.f; g_gcnt[i] = 0; }
}

// ---------------- W transpose: Wt[l][k][o] = Ws[l][o][k] ----------------
__global__ void wt_k(const float* __restrict__ Ws) {
    int i = blockIdx.x * blockDim.x + threadIdx.x;
    if (i >= N_LAYERS * D * D) return;
    int l = i / (D * D);
    int rem = i - l * (D * D);
    int o = rem / D;
    int k = rem - o * D;
    g_wt[l * D * D + k * D + o] = Ws[i];
}

// ---------------- degree histogram ----------------
__global__ void deg_k(const int* __restrict__ ei) {
    int e = blockIdx.x * blockDim.x + threadIdx.x;
    if (e >= N_EDGES) return;
    atomicAdd(&g_deg[ei[N_EDGES + e]], 1);
}

__global__ void dis_k() {
    int i = blockIdx.x * blockDim.x + threadIdx.x;
    if (i >= N_NODES) return;
    g_dis[i] = rsqrtf((float)(g_deg[i] + 1));   // +1 self loop
}

// ---------------- exclusive scan of g_deg -> g_off ----------------
__global__ void scan1_k() {
    __shared__ int sm[SCAN_BLK];
    int tid = threadIdx.x;
    int gid = blockIdx.x * SCAN_BLK + tid;
    int v = (gid < N_NODES) ? g_deg[gid] : 0;
    sm[tid] = v;
    __syncthreads();
    #pragma unroll
    for (int o = 1; o < SCAN_BLK; o <<= 1) {
        int t = (tid >= o) ? sm[tid - o] : 0;
        __syncthreads();
        sm[tid] += t;
        __syncthreads();
    }
    if (gid < N_NODES) g_off[gid] = sm[tid] - v;   // exclusive, block-local
    if (tid == SCAN_BLK - 1) g_bsum[blockIdx.x] = sm[tid];
}
__global__ void scan2_k() {
    if (threadIdx.x == 0) {
        int run = 0;
        for (int i = 0; i < SCAN_NBLK; i++) {
            int t = g_bsum[i];
            g_bsum[i] = run;
            run += t;
        }
    }
}
__global__ void scan3_k() {
    int gid = blockIdx.x * blockDim.x + threadIdx.x;
    if (gid < N_NODES) g_off[gid] += g_bsum[gid / SCAN_BLK];
    if (gid == 0) g_off[N_NODES] = N_EDGES;
}

// ---------------- counting-sort placement: group edges by dst ----------------
__global__ void place_k(const int* __restrict__ ei) {
    int e = blockIdx.x * blockDim.x + threadIdx.x;
    if (e >= N_EDGES) return;
    int r = ei[e];
    int c = ei[N_EDGES + e];
    int idx = g_off[c] + atomicAdd(&g_cur[c], 1);
    g_em[idx] = make_float2(__int_as_float(r), g_dis[r] * g_dis[c]);
}

// ---------------- SGEMM: H[n,128] = X[n,128] @ Wt (Wt is [k][o]) ----------------
__global__ void gemm_k(const float* __restrict__ X, const float* __restrict__ Wt,
                       float* __restrict__ H, int n) {
    extern __shared__ float sm[];
    float* xs = sm;             // [r][k]
    float* ws = sm + D * D;     // [k][o]

    int tid = threadIdx.x;
    int row0 = blockIdx.x * 128;

    #pragma unroll
    for (int it = 0; it < 16; it++) {
        int i = tid + it * 256;
        int r = i >> 5;
        int koff = (i & 31) << 2;
        int rg = row0 + r;
        float4 v = make_float4(0.f, 0.f, 0.f, 0.f);
        if (rg < n) v = *(const float4*)(X + rg * D + koff);
        ((float4*)xs)[i] = v;
    }
    #pragma unroll
    for (int it = 0; it < 16; it++) {
        int i = tid + it * 256;
        ((float4*)ws)[i] = ((const float4*)Wt)[i];
    }
    __syncthreads();

    int tx = tid & 15;
    int ty = tid >> 4;
    float acc[8][8];
    #pragma unroll
    for (int i = 0; i < 8; i++)
        #pragma unroll
        for (int j = 0; j < 8; j++) acc[i][j] = 0.f;

    const float* wsrow = ws + tx * 8;
    #pragma unroll 4
    for (int k = 0; k < D; k++) {
        float4 w0 = *(const float4*)(wsrow + k * D);
        float4 w1 = *(const float4*)(wsrow + k * D + 4);
        #pragma unroll
        for (int i = 0; i < 8; i++) {
            float xv = xs[(ty * 8 + i) * D + k];
            acc[i][0] += xv * w0.x; acc[i][1] += xv * w0.y;
            acc[i][2] += xv * w0.z; acc[i][3] += xv * w0.w;
            acc[i][4] += xv * w1.x; acc[i][5] += xv * w1.y;
            acc[i][6] += xv * w1.z; acc[i][7] += xv * w1.w;
        }
    }

    #pragma unroll
    for (int i = 0; i < 8; i++) {
        int r = row0 + ty * 8 + i;
        if (r < n) {
            *(float4*)(H + r * D + tx * 8)     = make_float4(acc[i][0], acc[i][1], acc[i][2], acc[i][3]);
            *(float4*)(H + r * D + tx * 8 + 4) = make_float4(acc[i][4], acc[i][5], acc[i][6], acc[i][7]);
        }
    }
}

// ---------------- fused gather + self-loop + bias + relu (atomic-free) ----------------
// one warp per destination node; each lane owns 4 features
__global__ void gather_k(const float* __restrict__ bias) {
    int gt = blockIdx.x * blockDim.x + threadIdx.x;
    int c = gt >> 5;
    int lane = gt & 31;
    if (c >= N_NODES) return;

    int s = g_off[c];
    int e = g_off[c + 1];
    float4 acc = make_float4(0.f, 0.f, 0.f, 0.f);

    int i = s;
    for (; i + 4 <= e; i += 4) {
        float2 m0 = g_em[i + 0];
        float2 m1 = g_em[i + 1];
        float2 m2 = g_em[i + 2];
        float2 m3 = g_em[i + 3];
        const float4 v0 = *(const float4*)(g_h + (size_t)__float_as_int(m0.x) * D + lane * 4);
        const float4 v1 = *(const float4*)(g_h + (size_t)__float_as_int(m1.x) * D + lane * 4);
        const float4 v2 = *(const float4*)(g_h + (size_t)__float_as_int(m2.x) * D + lane * 4);
        const float4 v3 = *(const float4*)(g_h + (size_t)__float_as_int(m3.x) * D + lane * 4);
        acc.x += m0.y * v0.x + m1.y * v1.x + m2.y * v2.x + m3.y * v3.x;
        acc.y += m0.y * v0.y + m1.y * v1.y + m2.y * v2.y + m3.y * v3.y;
        acc.z += m0.y * v0.z + m1.y * v1.z + m2.y * v2.z + m3.y * v3.z;
        acc.w += m0.y * v0.w + m1.y * v1.w + m2.y * v2.w + m3.y * v3.w;
    }
    for (; i < e; i++) {
        float2 m = g_em[i];
        const float4 v = *(const float4*)(g_h + (size_t)__float_as_int(m.x) * D + lane * 4);
        acc.x += m.y * v.x; acc.y += m.y * v.y; acc.z += m.y * v.z; acc.w += m.y * v.w;
    }

    float d = g_dis[c];
    float d2 = d * d;
    float4 h = *(const float4*)(g_h + (size_t)c * D + lane * 4);
    float4 b = ((const float4*)bias)[lane];
    float4 o;
    o.x = fmaxf(acc.x + d2 * h.x + b.x, 0.f);
    o.y = fmaxf(acc.y + d2 * h.y + b.y, 0.f);
    o.z = fmaxf(acc.z + d2 * h.z + b.z, 0.f);
    o.w = fmaxf(acc.w + d2 * h.w + b.w, 0.f);
    *(float4*)(g_x + (size_t)c * D + lane * 4) = o;
}

// ---------------- pooling ----------------
__global__ void pool_k(const int* __restrict__ batch, const float* __restrict__ lw) {
    int gt = blockIdx.x * blockDim.x + threadIdx.x;
    int node = gt >> 5;
    int lane = gt & 31;
    if (node >= N_NODES) return;
    float4 xv = ((const float4*)g_x)[node * 32 + lane];
    float4 wv = ((const float4*)lw)[lane];
    float s = xv.x * wv.x + xv.y * wv.y + xv.z * wv.z + xv.w * wv.w;
    #pragma unroll
    for (int o = 16; o > 0; o >>= 1) s += __shfl_xor_sync(0xFFFFFFFFu, s, o);
    if (lane == 0) {
        int g = batch[node];
        atomicAdd(&g_gsum[g], s);
        atomicAdd(&g_gcnt[g], 1);
    }
}

__global__ void final_k(const float* __restrict__ lb, float* __restrict__ out) {
    int g = blockIdx.x * blockDim.x + threadIdx.x;
    if (g >= N_GRAPHS) return;
    float c = fmaxf((float)g_gcnt[g], 1.0f);
    out[g] = g_gsum[g] / c + lb[0];
}

// ---------------- launcher ----------------
extern "C" void kernel_launch(void* const* d_in, const int* in_sizes, int n_in,
                              void* d_out, int out_size) {
    const float* x    = (const float*)d_in[0];
    const int*   ei   = (const int*)d_in[1];    // int32 (JAX x64 disabled)
    const int*   bat  = (const int*)d_in[2];
    const float* Ws   = (const float*)d_in[3];
    const float* bs   = (const float*)d_in[4];
    const float* lw   = (const float*)d_in[5];
    const float* lb   = (const float*)d_in[6];
    float*       out  = (float*)d_out;

    static bool attr_set = false;
    if (!attr_set) {
        cudaFuncSetAttribute(gemm_k, cudaFuncAttributeMaxDynamicSharedMemorySize,
                             2 * D * D * (int)sizeof(float));
        attr_set = true;
    }

    float *h_p, *x_p, *wt_p;
    cudaGetSymbolAddress((void**)&h_p,  g_h);
    cudaGetSymbolAddress((void**)&x_p,  g_x);
    cudaGetSymbolAddress((void**)&wt_p, g_wt);

    // prep
    zero_misc_k<<<(N_NODES + 255) / 256, 256>>>();
    wt_k<<<(N_LAYERS * D * D + 255) / 256, 256>>>(Ws);
    deg_k<<<(N_EDGES + 255) / 256, 256>>>(ei);
    dis_k<<<(N_NODES + 255) / 256, 256>>>();
    scan1_k<<<SCAN_NBLK, SCAN_BLK>>>();
    scan2_k<<<1, 32>>>();
    scan3_k<<<(N_NODES + 255) / 256, 256>>>();
    place_k<<<(N_EDGES + 255) / 256, 256>>>(ei);

    // layers
    const int gemm_blocks = (N_NODES + 127) / 128;
    const int smem = 2 * D * D * (int)sizeof(float);
    const int gather_blocks = (N_NODES * 32 + 255) / 256;

    for (int l = 0; l < N_LAYERS; l++) {
        const float* xin = (l == 0) ? x : x_p;
        gemm_k<<<gemm_blocks, 256, smem>>>(xin, wt_p + l * D * D, h_p, N_NODES);
        gather_k<<<gather_blocks, 256>>>(bs + l * D);
    }

    // pooling + output
    pool_k<<<(N_NODES * 32 + 255) / 256, 256>>>(bat, lw);
    final_k<<<(N_GRAPHS + 255) / 256, 256>>>(lb, out);
}